// round 1
// baseline (speedup 1.0000x reference)
#include <cuda_runtime.h>
#include <cuda_bf16.h>

#define OUTF 32
#define N_MAX 100000

// Scratch (device globals: allocation-free, graph-capturable)
__device__ float g_h[N_MAX * OUTF];      // 12.8 MB: h = norm_src * (sparse feat @ W)
__device__ int   g_outdeg[N_MAX];
__device__ int   g_indeg [N_MAX];

// ---------------------------------------------------------------------------
// K0: zero accumulators (d_out is poisoned each run; degrees must reset per replay)
__global__ void k_zero(float* __restrict__ out, int n_nodes, int out_elems) {
    int i = blockIdx.x * blockDim.x + threadIdx.x;
    int stride = gridDim.x * blockDim.x;
    for (int t = i; t < out_elems; t += stride) out[t] = 0.0f;
    for (int t = i; t < n_nodes; t += stride) { g_outdeg[t] = 0; g_indeg[t] = 0; }
}

// ---------------------------------------------------------------------------
// K1: out/in degree histograms
__global__ void k_deg(const int* __restrict__ src, const int* __restrict__ dst, int n_edges) {
    int i = blockIdx.x * blockDim.x + threadIdx.x;
    int stride = gridDim.x * blockDim.x;
    for (int e = i; e < n_edges; e += stride) {
        atomicAdd(&g_outdeg[src[e]], 1);
        atomicAdd(&g_indeg [dst[e]], 1);
    }
}

// ---------------------------------------------------------------------------
// K2: h[n,c] = outdeg(n)^-1/2 * sum_j val[n,j] * W[idx[n,j], c]
// One warp per node; lane c owns output channel c. W staged in smem
// (in_feats*32 floats = 32 KB). smem read sW[ij*32 + lane] is conflict-free
// (consecutive lanes -> consecutive banks). val/idx broadcast via shfl.
__global__ void k_feat(const float* __restrict__ vals, const int* __restrict__ idxs,
                       const float* __restrict__ W, int n_nodes, int in_feats, int kk) {
    extern __shared__ float sW[];
    for (int t = threadIdx.x; t < in_feats * OUTF; t += blockDim.x) sW[t] = W[t];
    __syncthreads();

    int lid  = threadIdx.x & 31;
    int wid  = threadIdx.x >> 5;
    int node = blockIdx.x * (blockDim.x >> 5) + wid;
    if (node >= n_nodes) return;

    // kk == 32 for this problem: each lane holds one (val, idx) pair
    float v  = vals[(long long)node * kk + lid];
    int   ix = idxs[(long long)node * kk + lid];

    float acc = 0.0f;
    #pragma unroll
    for (int j = 0; j < 32; j++) {
        float vj = __shfl_sync(0xffffffffu, v,  j);
        int   ij = __shfl_sync(0xffffffffu, ix, j);
        acc = fmaf(vj, sW[ij * OUTF + lid], acc);
    }

    float d = (float)g_outdeg[node];
    acc *= rsqrtf(fmaxf(d, 1.0f));
    g_h[node * OUTF + lid] = acc;
}

// ---------------------------------------------------------------------------
// K3: SpMM aggregation. 8 threads per edge; each thread moves one float4
// (32 floats/edge). h gather is a coalesced 128B read (L2-resident);
// accumulation via float4 atomicAdd (RED.128, sm_90+) -> 4x fewer atomics.
__global__ void k_spmm(const int* __restrict__ src, const int* __restrict__ dst,
                       float* __restrict__ out, int n_edges) {
    int gtid   = blockIdx.x * blockDim.x + threadIdx.x;
    int stride = gridDim.x * blockDim.x;
    int chunk  = gtid & 7;                       // which float4 of the 8
    for (int e = gtid >> 3; e < n_edges; e += (stride >> 3)) {
        int s = __ldg(&src[e]);
        int d = __ldg(&dst[e]);
        float4 hv = *reinterpret_cast<const float4*>(&g_h[s * OUTF + chunk * 4]);
        atomicAdd(reinterpret_cast<float4*>(&out[d * OUTF + chunk * 4]), hv);
    }
}

// ---------------------------------------------------------------------------
// K4: right-normalize by indeg^-1/2 and add bias
__global__ void k_fin(float* __restrict__ out, const float* __restrict__ bias, int n_nodes) {
    int i = blockIdx.x * blockDim.x + threadIdx.x;
    int stride = gridDim.x * blockDim.x;
    int total = n_nodes * OUTF;
    for (int t = i; t < total; t += stride) {
        float d = (float)g_indeg[t >> 5];          // OUTF == 32
        out[t] = out[t] * rsqrtf(fmaxf(d, 1.0f)) + bias[t & 31];
    }
}

// ---------------------------------------------------------------------------
extern "C" void kernel_launch(void* const* d_in, const int* in_sizes, int n_in,
                              void* d_out, int out_size) {
    const float* vals = (const float*)d_in[0];   // topk_values [N,K]
    const int*   idxs = (const int*)  d_in[1];   // topk_indices [N,K]
    const int*   src  = (const int*)  d_in[2];   // [E]
    const int*   dst  = (const int*)  d_in[3];   // [E]
    const float* W    = (const float*)d_in[4];   // [in_feats, 32]
    const float* bias = (const float*)d_in[5];   // [32]
    float* out = (float*)d_out;

    int n_nodes  = out_size / OUTF;              // 100000
    int n_edges  = in_sizes[2];                  // 1600000
    int in_feats = in_sizes[4] / OUTF;           // 256
    int kk       = in_sizes[0] / n_nodes;        // 32

    k_zero<<<512, 256>>>(out, n_nodes, out_size);
    k_deg <<<1024, 256>>>(src, dst, n_edges);

    const int warps_per_blk = 8;
    int feat_blocks = (n_nodes + warps_per_blk - 1) / warps_per_blk;
    size_t smem = (size_t)in_feats * OUTF * sizeof(float);   // 32 KB
    k_feat<<<feat_blocks, warps_per_blk * 32, smem>>>(vals, idxs, W, n_nodes, in_feats, kk);

    long long spmm_threads = (long long)n_edges * 8;
    int spmm_blocks = (int)((spmm_threads + 255) / 256);
    k_spmm<<<spmm_blocks, 256>>>(src, dst, out, n_edges);

    k_fin<<<1024, 256>>>(out, bias, n_nodes);
}

// round 2
// speedup vs baseline: 1.5749x; 1.5749x over previous
#include <cuda_runtime.h>
#include <cuda_bf16.h>

#define OUTF 32
#define N_MAX 100000

// Scratch (device globals: allocation-free, graph-capturable)
__device__ float g_h[N_MAX * OUTF];      // 12.8 MB: h = norm_src * (sparse feat @ W)
__device__ int   g_outdeg[N_MAX];
__device__ int   g_indeg [N_MAX];

// ---------------------------------------------------------------------------
// K0: zero accumulators (float4-vectorized; out_elems = 3.2M divisible by 4)
__global__ void k_zero(float4* __restrict__ out4, int n_nodes, int out_elems4) {
    int i = blockIdx.x * blockDim.x + threadIdx.x;
    int stride = gridDim.x * blockDim.x;
    float4 z = make_float4(0.f, 0.f, 0.f, 0.f);
    for (int t = i; t < out_elems4; t += stride) out4[t] = z;
    for (int t = i; t < n_nodes; t += stride) { g_outdeg[t] = 0; g_indeg[t] = 0; }
}

// ---------------------------------------------------------------------------
// K1: out/in degree histograms (int4 edge loads; n_edges divisible by 4 here,
// generic tail handled)
__global__ void k_deg(const int* __restrict__ src, const int* __restrict__ dst, int n_edges) {
    int i = blockIdx.x * blockDim.x + threadIdx.x;
    int stride = gridDim.x * blockDim.x;
    int n4 = n_edges >> 2;
    const int4* src4 = (const int4*)src;
    const int4* dst4 = (const int4*)dst;
    for (int e = i; e < n4; e += stride) {
        int4 s = src4[e];
        int4 d = dst4[e];
        atomicAdd(&g_outdeg[s.x], 1); atomicAdd(&g_outdeg[s.y], 1);
        atomicAdd(&g_outdeg[s.z], 1); atomicAdd(&g_outdeg[s.w], 1);
        atomicAdd(&g_indeg [d.x], 1); atomicAdd(&g_indeg [d.y], 1);
        atomicAdd(&g_indeg [d.z], 1); atomicAdd(&g_indeg [d.w], 1);
    }
    for (int e = (n4 << 2) + i; e < n_edges; e += stride) {
        atomicAdd(&g_outdeg[src[e]], 1);
        atomicAdd(&g_indeg [dst[e]], 1);
    }
}

// ---------------------------------------------------------------------------
// K2: h[n,c] = outdeg(n)^-1/2 * sum_j val[n,j] * W[idx[n,j], c]
// PERSISTENT: W staged into smem ONCE per block (592 blocks, not 12500),
// then grid-stride over nodes. One warp per node; lane c owns channel c.
__global__ void k_feat(const float* __restrict__ vals, const int* __restrict__ idxs,
                       const float* __restrict__ W, int n_nodes, int in_feats, int kk) {
    extern __shared__ float sW[];
    for (int t = threadIdx.x; t < in_feats * OUTF; t += blockDim.x) sW[t] = W[t];
    __syncthreads();

    int lid   = threadIdx.x & 31;
    int wid   = threadIdx.x >> 5;
    int wpb   = blockDim.x >> 5;
    int gwid  = blockIdx.x * wpb + wid;
    int nwarp = gridDim.x * wpb;

    for (int node = gwid; node < n_nodes; node += nwarp) {
        // kk == 32: each lane holds one (val, idx) pair, coalesced load
        float v  = vals[(long long)node * kk + lid];
        int   ix = idxs[(long long)node * kk + lid];

        float acc = 0.0f;
        #pragma unroll
        for (int j = 0; j < 32; j++) {
            float vj = __shfl_sync(0xffffffffu, v,  j);
            int   ij = __shfl_sync(0xffffffffu, ix, j);
            acc = fmaf(vj, sW[ij * OUTF + lid], acc);
        }

        float d = (float)g_outdeg[node];
        acc *= rsqrtf(fmaxf(d, 1.0f));
        g_h[node * OUTF + lid] = acc;
    }
}

// ---------------------------------------------------------------------------
// K3: SpMM aggregation. 8 threads per edge, one float4 each (1 L1 line per
// edge gather, coalesced). Accumulate via float4 atomicAdd (RED.128).
__global__ void k_spmm(const int* __restrict__ src, const int* __restrict__ dst,
                       float* __restrict__ out, int n_edges) {
    int gtid   = blockIdx.x * blockDim.x + threadIdx.x;
    int stride = gridDim.x * blockDim.x;
    int chunk  = gtid & 7;
    for (int e = gtid >> 3; e < n_edges; e += (stride >> 3)) {
        int s = __ldg(&src[e]);
        int d = __ldg(&dst[e]);
        float4 hv = *reinterpret_cast<const float4*>(&g_h[s * OUTF + chunk * 4]);
        atomicAdd(reinterpret_cast<float4*>(&out[d * OUTF + chunk * 4]), hv);
    }
}

// ---------------------------------------------------------------------------
// K4: right-normalize by indeg^-1/2 and add bias (float4-vectorized;
// 4 consecutive floats always belong to the same node since OUTF=32)
__global__ void k_fin(float4* __restrict__ out4, const float* __restrict__ bias, int n_nodes) {
    int i = blockIdx.x * blockDim.x + threadIdx.x;
    int stride = gridDim.x * blockDim.x;
    int total4 = n_nodes * (OUTF / 4);
    for (int t = i; t < total4; t += stride) {
        int node = t >> 3;                 // 8 float4 per node
        int c4   = (t & 7) << 2;           // starting channel
        float d  = (float)g_indeg[node];
        float r  = rsqrtf(fmaxf(d, 1.0f));
        float4 o = out4[t];
        o.x = o.x * r + bias[c4 + 0];
        o.y = o.y * r + bias[c4 + 1];
        o.z = o.z * r + bias[c4 + 2];
        o.w = o.w * r + bias[c4 + 3];
        out4[t] = o;
    }
}

// ---------------------------------------------------------------------------
extern "C" void kernel_launch(void* const* d_in, const int* in_sizes, int n_in,
                              void* d_out, int out_size) {
    const float* vals = (const float*)d_in[0];   // topk_values [N,K]
    const int*   idxs = (const int*)  d_in[1];   // topk_indices [N,K]
    const int*   src  = (const int*)  d_in[2];   // [E]
    const int*   dst  = (const int*)  d_in[3];   // [E]
    const float* W    = (const float*)d_in[4];   // [in_feats, 32]
    const float* bias = (const float*)d_in[5];   // [32]
    float* out = (float*)d_out;

    int n_nodes  = out_size / OUTF;              // 100000
    int n_edges  = in_sizes[2];                  // 1600000
    int in_feats = in_sizes[4] / OUTF;           // 256
    int kk       = in_sizes[0] / n_nodes;        // 32

    k_zero<<<512, 256>>>((float4*)out, n_nodes, out_size / 4);
    k_deg <<<1024, 256>>>(src, dst, n_edges);

    // Persistent feat kernel: 592 blocks (~4/SM), W staged once per block
    size_t smem = (size_t)in_feats * OUTF * sizeof(float);   // 32 KB
    k_feat<<<592, 256, smem>>>(vals, idxs, W, n_nodes, in_feats, kk);

    long long spmm_threads = (long long)n_edges * 8;
    int spmm_blocks = (int)((spmm_threads + 255) / 256);
    k_spmm<<<spmm_blocks, 256>>>(src, dst, out, n_edges);

    k_fin<<<1024, 256>>>((float4*)out, bias, n_nodes);
}